// round 13
// baseline (speedup 1.0000x reference)
#include <cuda_runtime.h>
#include <cuda_fp16.h>
#include <cstdint>

#define NN 50000
#define NE_IN 800000
#define NE (NE_IN + NN)
#define DD 128
#define NG 64
#define NC 10
#define NL 5

#define SCAN_BLOCKS ((NN + 1023) / 1024)

// ---------------- static device scratch ----------------
__device__ __align__(16) __half g_bufA[NN * DD];
__device__ __align__(16) __half g_bufB[NN * DD];
__device__ __align__(16) __half g_xlh[NN * DD];
__device__ __align__(16) float  g_xr[NN * DD];
__device__ __align__(16) __half g_WpackH[NL * 256 * DD];  // [l][n][k]
__device__ __align__(16) float  g_bpack[NL * 256];
__device__ int   g_rowptr[NN + 1];
__device__ int   g_cursor[NN];
__device__ int   g_esrc[NE];
__device__ int   g_cnt[NN];
__device__ int   g_bsum[64];
__device__ __align__(16) float g_pool[NG * DD];
__device__ float g_pcnt[NG];

// ---------------- init ----------------
__global__ void init_kernel() {
    int i = blockIdx.x * blockDim.x + threadIdx.x;
    if (i < NN) g_cnt[i] = 0;
    if (i < NG * DD) g_pool[i] = 0.f;
    if (i < NG) g_pcnt[i] = 0.f;
}

// ---------------- convert x -> fp16 bufB ----------------
__global__ void roundx_kernel(const float* __restrict__ x) {
    int i = blockIdx.x * blockDim.x + threadIdx.x;
    if (i < NN * DD / 4) {
        float4 v = ((const float4*)x)[i];
        ((__half2*)g_bufB)[2 * i]     = __floats2half2_rn(v.x, v.y);
        ((__half2*)g_bufB)[2 * i + 1] = __floats2half2_rn(v.z, v.w);
    }
}

// ---------------- CSR build ----------------
__global__ void count_kernel(const int* __restrict__ ei) {
    int e = blockIdx.x * blockDim.x + threadIdx.x;
    if (e >= NE) return;
    int d = (e < NE_IN) ? ei[NE_IN + e] : (e - NE_IN);
    atomicAdd(&g_cnt[d], 1);
}

__global__ void scan1_kernel() {
    __shared__ int wsum[32];
    int tid = threadIdx.x;
    int i = blockIdx.x * 1024 + tid;
    int v = (i < NN) ? g_cnt[i] : 0;
    int x = v;
#pragma unroll
    for (int off = 1; off < 32; off <<= 1) {
        int y = __shfl_up_sync(0xffffffffu, x, off);
        if ((tid & 31) >= off) x += y;
    }
    if ((tid & 31) == 31) wsum[tid >> 5] = x;
    __syncthreads();
    if (tid < 32) {
        int w = wsum[tid];
        int xs = w;
#pragma unroll
        for (int off = 1; off < 32; off <<= 1) {
            int y = __shfl_up_sync(0xffffffffu, xs, off);
            if (tid >= off) xs += y;
        }
        wsum[tid] = xs - w;
    }
    __syncthreads();
    int incl = x + wsum[tid >> 5];
    if (i < NN) g_rowptr[i] = incl - v;
    if (tid == 1023) g_bsum[blockIdx.x] = incl;
}

__global__ void scan2_kernel() {
    if (threadIdx.x == 0) {
        int acc = 0;
        for (int b = 0; b < SCAN_BLOCKS; b++) { int t = g_bsum[b]; g_bsum[b] = acc; acc += t; }
    }
}

__global__ void scan3_kernel() {
    int i = blockIdx.x * 1024 + threadIdx.x;
    if (i < NN) {
        int r = g_rowptr[i] + g_bsum[blockIdx.x];
        g_rowptr[i] = r;
        g_cursor[i] = r;
    }
    if (i == 0) g_rowptr[NN] = NE;
}

__global__ void scatter_kernel(const int* __restrict__ ei) {
    int e = blockIdx.x * blockDim.x + threadIdx.x;
    if (e >= NE) return;
    int s, d;
    if (e < NE_IN) { s = ei[e]; d = ei[NE_IN + e]; }
    else           { s = e - NE_IN; d = s; }
    int pos = atomicAdd(&g_cursor[d], 1);
    g_esrc[pos] = s;
}

// ---------------- pack weights: fp16, transposed [l][n][k] ----------------
__global__ void pack_kernel(const float* __restrict__ Wl, const float* __restrict__ bl,
                            const float* __restrict__ Wr, const float* __restrict__ br) {
    int i = blockIdx.x * blockDim.x + threadIdx.x;
    int WTOT = NL * 256 * DD;
    if (i < WTOT) {
        int l = i / (256 * DD);
        int rem = i - l * 256 * DD;
        int n = rem >> 7, k = rem & 127;
        float w = (n < DD) ? Wl[(l * DD + k) * DD + n]
                           : Wr[(l * DD + k) * DD + (n - DD)];
        g_WpackH[i] = __float2half_rn(w);
    } else if (i < WTOT + NL * 256) {
        int r = i - WTOT;
        int l = r >> 8, j = r & 255;
        g_bpack[r] = (j < DD) ? bl[l * DD + j] : br[l * DD + j - DD];
    }
}

// ---------------- fp16 tensor-core GEMM, m16n8k16, BK=32, 2-stage ----------------
#define GBM 128
#define GBN 64
#define GBK 32
#define NKT (DD / GBK)
#define APAD 40
#define BPAD 40

__device__ __forceinline__ void cpa16(void* smem, const void* g) {
    unsigned sa = (unsigned)__cvta_generic_to_shared(smem);
    asm volatile("cp.async.cg.shared.global [%0], [%1], 16;" :: "r"(sa), "l"(g));
}
__device__ __forceinline__ void mma16h(float* c, const uint32_t* a, const uint32_t* b) {
    asm volatile(
        "mma.sync.aligned.m16n8k16.row.col.f32.f16.f16.f32 "
        "{%0,%1,%2,%3},{%4,%5,%6,%7},{%8,%9},{%0,%1,%2,%3};"
        : "+f"(c[0]), "+f"(c[1]), "+f"(c[2]), "+f"(c[3])
        : "r"(a[0]), "r"(a[1]), "r"(a[2]), "r"(a[3]), "r"(b[0]), "r"(b[1]));
}

__global__ __launch_bounds__(256) void gemm_tc_kernel(int l) {
    const __half* A = (l & 1) ? g_bufA : g_bufB;
    __shared__ __half As[2][GBM][APAD];
    __shared__ __half Bs[2][GBN][BPAD];

    int tid  = threadIdx.x;
    int lane = tid & 31;
    int warp = tid >> 5;
    int wm = warp >> 1, wn = warp & 1;
    int g = lane >> 2, t = lane & 3;
    int bm0 = blockIdx.x * GBM;

    const __half* WbT = g_WpackH + l * (256 * DD) + (size_t)(blockIdx.y * GBN) * DD;

    float acc[2][4][4];
#pragma unroll
    for (int mt = 0; mt < 2; mt++)
#pragma unroll
        for (int nt = 0; nt < 4; nt++)
#pragma unroll
            for (int c = 0; c < 4; c++) acc[mt][nt][c] = 0.f;

    auto load_stage = [&](int buf, int k0) {
#pragma unroll
        for (int i = 0; i < 2; i++) {
            int idx = tid + i * 256;
            int row = idx >> 2, q = idx & 3;
            int gr = bm0 + row; if (gr >= NN) gr = NN - 1;
            cpa16(&As[buf][row][q * 8], A + (size_t)gr * DD + k0 + q * 8);
        }
        {
            int row = tid >> 2, q = tid & 3;
            cpa16(&Bs[buf][row][q * 8], WbT + (size_t)row * DD + k0 + q * 8);
        }
        asm volatile("cp.async.commit_group;");
    };

    load_stage(0, 0);

    int buf = 0;
#pragma unroll
    for (int kt = 0; kt < NKT; kt++) {
        if (kt + 1 < NKT) {
            load_stage(buf ^ 1, (kt + 1) * GBK);
            asm volatile("cp.async.wait_group 1;");
        } else {
            asm volatile("cp.async.wait_group 0;");
        }
        __syncthreads();

#pragma unroll
        for (int ks = 0; ks < 2; ks++) {
            int kk = ks * 16;
            uint32_t af[2][4];
#pragma unroll
            for (int mt = 0; mt < 2; mt++) {
                int r0 = wm * 32 + mt * 16 + g;
                af[mt][0] = *(const uint32_t*)&As[buf][r0][kk + 2 * t];
                af[mt][1] = *(const uint32_t*)&As[buf][r0 + 8][kk + 2 * t];
                af[mt][2] = *(const uint32_t*)&As[buf][r0][kk + 2 * t + 8];
                af[mt][3] = *(const uint32_t*)&As[buf][r0 + 8][kk + 2 * t + 8];
            }
            uint32_t bf[4][2];
#pragma unroll
            for (int nt = 0; nt < 4; nt++) {
                int c0 = wn * 32 + nt * 8 + g;
                bf[nt][0] = *(const uint32_t*)&Bs[buf][c0][kk + 2 * t];
                bf[nt][1] = *(const uint32_t*)&Bs[buf][c0][kk + 2 * t + 8];
            }
#pragma unroll
            for (int mt = 0; mt < 2; mt++)
#pragma unroll
                for (int nt = 0; nt < 4; nt++)
                    mma16h(acc[mt][nt], af[mt], bf[nt]);
        }
        __syncthreads();
        buf ^= 1;
    }

    int cbase = blockIdx.y * GBN + wn * 32;
    const float* bp = g_bpack + l * 256;
    bool isXL = (blockIdx.y < 2);
    int coff = isXL ? cbase : cbase - DD;
#pragma unroll
    for (int mt = 0; mt < 2; mt++) {
        int r0 = bm0 + wm * 32 + mt * 16 + g;
#pragma unroll
        for (int nt = 0; nt < 4; nt++) {
            int cb = cbase + nt * 8 + 2 * t;
            int c  = coff + nt * 8 + 2 * t;
            float bx = bp[cb], by = bp[cb + 1];
            if (r0 < NN) {
                float vx = acc[mt][nt][0] + bx, vy = acc[mt][nt][1] + by;
                if (isXL) *(__half2*)(g_xlh + (size_t)r0 * DD + c) = __floats2half2_rn(vx, vy);
                else      *(float2*)(g_xr + (size_t)r0 * DD + c) = make_float2(vx, vy);
            }
            if (r0 + 8 < NN) {
                float vx = acc[mt][nt][2] + bx, vy = acc[mt][nt][3] + by;
                if (isXL) *(__half2*)(g_xlh + (size_t)(r0 + 8) * DD + c) = __floats2half2_rn(vx, vy);
                else      *(float2*)(g_xr + (size_t)(r0 + 8) * DD + c) = make_float2(vx, vy);
            }
        }
    }
}

// ---------------- GAT edge aggregation (fp16 gathers, depth-2 data prefetch) ----------------
__device__ __forceinline__ float lrl(float z) { return z > 0.f ? z : 0.2f * z; }

__global__ __launch_bounds__(256) void gat_kernel(const float* __restrict__ attb,
                                                  const float* __restrict__ biasb,
                                                  int outbuf) {
    int gw = (blockIdx.x * blockDim.x + threadIdx.x) >> 5;
    int lane = threadIdx.x & 31;
    if (gw >= NN) return;
    __half* hout = (outbuf == 0) ? g_bufA : g_bufB;

    int slot = lane >> 3, h = lane & 7;

    float at[16], xr[16], ac[16];
#pragma unroll
    for (int c = 0; c < 4; c++) {
        float4 a4 = ((const float4*)(attb + h * 16))[c];
        at[4 * c + 0] = a4.x; at[4 * c + 1] = a4.y; at[4 * c + 2] = a4.z; at[4 * c + 3] = a4.w;
        float4 r4 = ((const float4*)(g_xr + (size_t)gw * DD + h * 16))[c];
        xr[4 * c + 0] = r4.x; xr[4 * c + 1] = r4.y; xr[4 * c + 2] = r4.z; xr[4 * c + 3] = r4.w;
    }
#pragma unroll
    for (int c = 0; c < 16; c++) ac[c] = 0.f;

    int jb = g_rowptr[gw], je = g_rowptr[gw + 1];
    float s = 0.f;

    int jbase = jb + slot;
    int nIter = (je - jb + 3) >> 2;

    // prologue: data for iters 0 and 1 in flight; index for iter 2
    int sA = __ldg(&g_esrc[jbase < je ? jbase : je - 1]);
    const uint4* pA = (const uint4*)(g_xlh + (size_t)sA * DD + h * 16);
    uint4 uA0 = __ldg(pA), uA1 = __ldg(pA + 1);
    int t1 = jbase + 4;
    int sB = __ldg(&g_esrc[t1 < je ? t1 : je - 1]);
    const uint4* pB = (const uint4*)(g_xlh + (size_t)sB * DD + h * 16);
    uint4 uB0 = __ldg(pB), uB1 = __ldg(pB + 1);
    int t2 = jbase + 8;
    int sC = __ldg(&g_esrc[t2 < je ? t2 : je - 1]);
    int jn = jbase + 12;

    for (int it = 0; it < nIter; it++) {
        // issue data load for iter it+2 and index for it+3
        const uint4* pC = (const uint4*)(g_xlh + (size_t)sC * DD + h * 16);
        uint4 vC0 = __ldg(pC), vC1 = __ldg(pC + 1);
        sC = __ldg(&g_esrc[jn < je ? jn : je - 1]);
        jn += 4;

        bool act = (jbase + 4 * it < je);

        float xs[16];
        {
            const __half2* hh0 = (const __half2*)&uA0;
            const __half2* hh1 = (const __half2*)&uA1;
#pragma unroll
            for (int k = 0; k < 4; k++) {
                float2 f = __half22float2(hh0[k]);
                xs[2 * k] = f.x; xs[2 * k + 1] = f.y;
            }
#pragma unroll
            for (int k = 0; k < 4; k++) {
                float2 f = __half22float2(hh1[k]);
                xs[8 + 2 * k] = f.x; xs[8 + 2 * k + 1] = f.y;
            }
        }

        float d = 0.f;
#pragma unroll
        for (int c = 0; c < 16; c++) d += at[c] * lrl(xs[c] + xr[c]);

        float p = act ? __expf(d) : 0.f;
        s += p;
#pragma unroll
        for (int c = 0; c < 16; c++) ac[c] += p * xs[c];

        uA0 = uB0; uA1 = uB1;
        uB0 = vC0; uB1 = vC1;
    }

    // merge 4 slots
#pragma unroll
    for (int off = 8; off <= 16; off <<= 1) {
        s += __shfl_xor_sync(0xffffffffu, s, off);
#pragma unroll
        for (int c = 0; c < 16; c++) ac[c] += __shfl_xor_sync(0xffffffffu, ac[c], off);
    }

    if (slot == 0) {
        float inv = 1.f / s;
        __half2 oh[8];
#pragma unroll
        for (int c = 0; c < 4; c++) {
            float4 b4 = ((const float4*)(biasb + h * 16))[c];
            float o0 = ac[4 * c + 0] * inv + b4.x;
            float o1 = ac[4 * c + 1] * inv + b4.y;
            float o2 = ac[4 * c + 2] * inv + b4.z;
            float o3 = ac[4 * c + 3] * inv + b4.w;
            o0 = o0 > 0.f ? o0 : (__expf(o0) - 1.f);
            o1 = o1 > 0.f ? o1 : (__expf(o1) - 1.f);
            o2 = o2 > 0.f ? o2 : (__expf(o2) - 1.f);
            o3 = o3 > 0.f ? o3 : (__expf(o3) - 1.f);
            oh[2 * c]     = __floats2half2_rn(o0, o1);
            oh[2 * c + 1] = __floats2half2_rn(o2, o3);
        }
        uint4* op = (uint4*)(hout + (size_t)gw * DD + h * 16);
        op[0] = *(uint4*)&oh[0];
        op[1] = *(uint4*)&oh[4];
    }
}

// ---------------- global mean pool (reads fp16 h) ----------------
__global__ __launch_bounds__(128) void pool_kernel(const int* __restrict__ batch) {
    int ch = threadIdx.x;
    int n0 = blockIdx.x * 128;
    int nEnd = n0 + 128; if (nEnd > NN) nEnd = NN;
    if (n0 >= NN) return;

    int cur = batch[n0];
    float acc = 0.f;
    int runlen = 0;
    for (int nd = n0; nd < nEnd; nd++) {
        int gidx = batch[nd];
        if (gidx != cur) {
            atomicAdd(&g_pool[cur * DD + ch], acc);
            if (ch == 0) atomicAdd(&g_pcnt[cur], (float)runlen);
            acc = 0.f; runlen = 0; cur = gidx;
        }
        acc += __half2float(g_bufA[(size_t)nd * DD + ch]);
        runlen++;
    }
    atomicAdd(&g_pool[cur * DD + ch], acc);
    if (ch == 0) atomicAdd(&g_pcnt[cur], (float)runlen);
}

// ---------------- classifier + log_softmax ----------------
__global__ void cls_kernel(const float* __restrict__ Wout,
                           const float* __restrict__ bout,
                           float* __restrict__ out) {
    __shared__ float slog[NG][NC];
    __shared__ float srow[NG];
    int t = threadIdx.x;
    if (t < NG * NC) {
        int g = t / NC, c = t % NC;
        float inv = 1.f / fmaxf(g_pcnt[g], 1.f);
        float acc = 0.f;
        for (int k = 0; k < DD; k++) acc += g_pool[g * DD + k] * Wout[k * NC + c];
        slog[g][c] = acc * inv + bout[c];
    }
    __syncthreads();
    if (t < NG) {
        float mx = -3.0e38f;
        for (int c = 0; c < NC; c++) mx = fmaxf(mx, slog[t][c]);
        float ssum = 0.f;
        for (int c = 0; c < NC; c++) ssum += expf(slog[t][c] - mx);
        srow[t] = mx + logf(ssum);
    }
    __syncthreads();
    if (t < NG * NC) out[t] = slog[t / NC][t % NC] - srow[t / NC];
}

// ---------------- driver ----------------
extern "C" void kernel_launch(void* const* d_in, const int* in_sizes, int n_in,
                              void* d_out, int out_size) {
    const float* x     = (const float*)d_in[0];
    const int*   ei    = (const int*)  d_in[1];
    const int*   batch = (const int*)  d_in[2];
    const float* Wl    = (const float*)d_in[3];
    const float* bl    = (const float*)d_in[4];
    const float* Wr    = (const float*)d_in[5];
    const float* br    = (const float*)d_in[6];
    const float* att   = (const float*)d_in[7];
    const float* bias  = (const float*)d_in[8];
    const float* Wout  = (const float*)d_in[9];
    const float* bout  = (const float*)d_in[10];
    float* out = (float*)d_out;

    // side stream + events for the independent CSR branch (created once; host-side
    // objects only, no device memory)
    static cudaStream_t s2 = nullptr;
    static cudaEvent_t evFork = nullptr, evJoin = nullptr;
    if (s2 == nullptr) {
        cudaStreamCreateWithFlags(&s2, cudaStreamNonBlocking);
        cudaEventCreateWithFlags(&evFork, cudaEventDisableTiming);
        cudaEventCreateWithFlags(&evJoin, cudaEventDisableTiming);
    }

    dim3 ggrid((NN + GBM - 1) / GBM, 4);

    // fork: CSR branch on s2
    cudaEventRecord(evFork, 0);
    cudaStreamWaitEvent(s2, evFork, 0);

    // submission order keeps gemm0 at kernel-launch slot #3 for ncu capture
    init_kernel<<<(NN + 255) / 256, 256, 0, s2>>>();                       // #0
    pack_kernel<<<(NL * 256 * DD + NL * 256 + 255) / 256, 256>>>(Wl, bl, Wr, br); // #1
    roundx_kernel<<<(NN * DD / 4 + 255) / 256, 256>>>(x);                  // #2
    gemm_tc_kernel<<<ggrid, 256>>>(0);                                     // #3

    count_kernel<<<(NE + 255) / 256, 256, 0, s2>>>(ei);
    scan1_kernel<<<SCAN_BLOCKS, 1024, 0, s2>>>();
    scan2_kernel<<<1, 32, 0, s2>>>();
    scan3_kernel<<<SCAN_BLOCKS, 1024, 0, s2>>>();
    scatter_kernel<<<(NE + 255) / 256, 256, 0, s2>>>(ei);
    cudaEventRecord(evJoin, s2);

    // join: everything after here needs the CSR
    cudaStreamWaitEvent(0, evJoin, 0);

    for (int l = 0; l < NL; l++) {
        if (l > 0) gemm_tc_kernel<<<ggrid, 256>>>(l);
        int outbuf = (l % 2 == 0) ? 0 : 1;
        gat_kernel<<<(NN * 32 + 255) / 256, 256>>>(att + l * DD, bias + l * DD, outbuf);
    }

    pool_kernel<<<(NN + 127) / 128, 128>>>(batch);
    cls_kernel<<<1, 640>>>(Wout, bout, out);
}

// round 14
// speedup vs baseline: 1.1613x; 1.1613x over previous
#include <cuda_runtime.h>
#include <cuda_fp16.h>
#include <cstdint>

#define NN 50000
#define NE_IN 800000
#define NE (NE_IN + NN)
#define DD 128
#define NG 64
#define NC 10
#define NL 5

#define SCAN_BLOCKS ((NN + 1023) / 1024)

// ---------------- static device scratch ----------------
__device__ __align__(16) __half g_bufA[NN * DD];
__device__ __align__(16) __half g_bufB[NN * DD];
__device__ __align__(16) __half g_xlh[NN * DD];
__device__ __align__(16) float  g_xr[NN * DD];
__device__ __align__(16) __half g_WpackH[NL * 256 * DD];  // [l][n][k]
__device__ __align__(16) float  g_bpack[NL * 256];
__device__ int   g_rowptr[NN + 1];
__device__ int   g_cursor[NN];
__device__ int   g_esrc[NE];
__device__ int   g_cnt[NN];
__device__ int   g_bsum[64];
__device__ __align__(16) float g_pool[NG * DD];
__device__ float g_pcnt[NG];

// ---------------- init ----------------
__global__ void init_kernel() {
    int i = blockIdx.x * blockDim.x + threadIdx.x;
    if (i < NN) g_cnt[i] = 0;
    if (i < NG * DD) g_pool[i] = 0.f;
    if (i < NG) g_pcnt[i] = 0.f;
}

// ---------------- convert x -> fp16 bufB ----------------
__global__ void roundx_kernel(const float* __restrict__ x) {
    int i = blockIdx.x * blockDim.x + threadIdx.x;
    if (i < NN * DD / 4) {
        float4 v = ((const float4*)x)[i];
        ((__half2*)g_bufB)[2 * i]     = __floats2half2_rn(v.x, v.y);
        ((__half2*)g_bufB)[2 * i + 1] = __floats2half2_rn(v.z, v.w);
    }
}

// ---------------- CSR build ----------------
__global__ void count_kernel(const int* __restrict__ ei) {
    int e = blockIdx.x * blockDim.x + threadIdx.x;
    if (e >= NE) return;
    int d = (e < NE_IN) ? ei[NE_IN + e] : (e - NE_IN);
    atomicAdd(&g_cnt[d], 1);
}

__global__ void scan1_kernel() {
    __shared__ int wsum[32];
    int tid = threadIdx.x;
    int i = blockIdx.x * 1024 + tid;
    int v = (i < NN) ? g_cnt[i] : 0;
    int x = v;
#pragma unroll
    for (int off = 1; off < 32; off <<= 1) {
        int y = __shfl_up_sync(0xffffffffu, x, off);
        if ((tid & 31) >= off) x += y;
    }
    if ((tid & 31) == 31) wsum[tid >> 5] = x;
    __syncthreads();
    if (tid < 32) {
        int w = wsum[tid];
        int xs = w;
#pragma unroll
        for (int off = 1; off < 32; off <<= 1) {
            int y = __shfl_up_sync(0xffffffffu, xs, off);
            if (tid >= off) xs += y;
        }
        wsum[tid] = xs - w;
    }
    __syncthreads();
    int incl = x + wsum[tid >> 5];
    if (i < NN) g_rowptr[i] = incl - v;
    if (tid == 1023) g_bsum[blockIdx.x] = incl;
}

__global__ void scan2_kernel() {
    if (threadIdx.x == 0) {
        int acc = 0;
        for (int b = 0; b < SCAN_BLOCKS; b++) { int t = g_bsum[b]; g_bsum[b] = acc; acc += t; }
    }
}

__global__ void scan3_kernel() {
    int i = blockIdx.x * 1024 + threadIdx.x;
    if (i < NN) {
        int r = g_rowptr[i] + g_bsum[blockIdx.x];
        g_rowptr[i] = r;
        g_cursor[i] = r;
    }
    if (i == 0) g_rowptr[NN] = NE;
}

__global__ void scatter_kernel(const int* __restrict__ ei) {
    int e = blockIdx.x * blockDim.x + threadIdx.x;
    if (e >= NE) return;
    int s, d;
    if (e < NE_IN) { s = ei[e]; d = ei[NE_IN + e]; }
    else           { s = e - NE_IN; d = s; }
    int pos = atomicAdd(&g_cursor[d], 1);
    g_esrc[pos] = s;
}

// ---------------- pack weights: fp16, transposed [l][n][k] ----------------
__global__ void pack_kernel(const float* __restrict__ Wl, const float* __restrict__ bl,
                            const float* __restrict__ Wr, const float* __restrict__ br) {
    int i = blockIdx.x * blockDim.x + threadIdx.x;
    int WTOT = NL * 256 * DD;
    if (i < WTOT) {
        int l = i / (256 * DD);
        int rem = i - l * 256 * DD;
        int n = rem >> 7, k = rem & 127;
        float w = (n < DD) ? Wl[(l * DD + k) * DD + n]
                           : Wr[(l * DD + k) * DD + (n - DD)];
        g_WpackH[i] = __float2half_rn(w);
    } else if (i < WTOT + NL * 256) {
        int r = i - WTOT;
        int l = r >> 8, j = r & 255;
        g_bpack[r] = (j < DD) ? bl[l * DD + j] : br[l * DD + j - DD];
    }
}

// ---------------- fp16 tensor-core GEMM, m16n8k16, BK=32, 2-stage ----------------
#define GBM 128
#define GBN 64
#define GBK 32
#define NKT (DD / GBK)
#define APAD 40
#define BPAD 40

__device__ __forceinline__ void cpa16(void* smem, const void* g) {
    unsigned sa = (unsigned)__cvta_generic_to_shared(smem);
    asm volatile("cp.async.cg.shared.global [%0], [%1], 16;" :: "r"(sa), "l"(g));
}
__device__ __forceinline__ void mma16h(float* c, const uint32_t* a, const uint32_t* b) {
    asm volatile(
        "mma.sync.aligned.m16n8k16.row.col.f32.f16.f16.f32 "
        "{%0,%1,%2,%3},{%4,%5,%6,%7},{%8,%9},{%0,%1,%2,%3};"
        : "+f"(c[0]), "+f"(c[1]), "+f"(c[2]), "+f"(c[3])
        : "r"(a[0]), "r"(a[1]), "r"(a[2]), "r"(a[3]), "r"(b[0]), "r"(b[1]));
}

__global__ __launch_bounds__(256) void gemm_tc_kernel(int l) {
    const __half* A = (l & 1) ? g_bufA : g_bufB;
    __shared__ __half As[2][GBM][APAD];
    __shared__ __half Bs[2][GBN][BPAD];

    int tid  = threadIdx.x;
    int lane = tid & 31;
    int warp = tid >> 5;
    int wm = warp >> 1, wn = warp & 1;
    int g = lane >> 2, t = lane & 3;
    int bm0 = blockIdx.x * GBM;

    const __half* WbT = g_WpackH + l * (256 * DD) + (size_t)(blockIdx.y * GBN) * DD;

    float acc[2][4][4];
#pragma unroll
    for (int mt = 0; mt < 2; mt++)
#pragma unroll
        for (int nt = 0; nt < 4; nt++)
#pragma unroll
            for (int c = 0; c < 4; c++) acc[mt][nt][c] = 0.f;

    auto load_stage = [&](int buf, int k0) {
#pragma unroll
        for (int i = 0; i < 2; i++) {
            int idx = tid + i * 256;
            int row = idx >> 2, q = idx & 3;
            int gr = bm0 + row; if (gr >= NN) gr = NN - 1;
            cpa16(&As[buf][row][q * 8], A + (size_t)gr * DD + k0 + q * 8);
        }
        {
            int row = tid >> 2, q = tid & 3;
            cpa16(&Bs[buf][row][q * 8], WbT + (size_t)row * DD + k0 + q * 8);
        }
        asm volatile("cp.async.commit_group;");
    };

    load_stage(0, 0);

    int buf = 0;
#pragma unroll
    for (int kt = 0; kt < NKT; kt++) {
        if (kt + 1 < NKT) {
            load_stage(buf ^ 1, (kt + 1) * GBK);
            asm volatile("cp.async.wait_group 1;");
        } else {
            asm volatile("cp.async.wait_group 0;");
        }
        __syncthreads();

#pragma unroll
        for (int ks = 0; ks < 2; ks++) {
            int kk = ks * 16;
            uint32_t af[2][4];
#pragma unroll
            for (int mt = 0; mt < 2; mt++) {
                int r0 = wm * 32 + mt * 16 + g;
                af[mt][0] = *(const uint32_t*)&As[buf][r0][kk + 2 * t];
                af[mt][1] = *(const uint32_t*)&As[buf][r0 + 8][kk + 2 * t];
                af[mt][2] = *(const uint32_t*)&As[buf][r0][kk + 2 * t + 8];
                af[mt][3] = *(const uint32_t*)&As[buf][r0 + 8][kk + 2 * t + 8];
            }
            uint32_t bf[4][2];
#pragma unroll
            for (int nt = 0; nt < 4; nt++) {
                int c0 = wn * 32 + nt * 8 + g;
                bf[nt][0] = *(const uint32_t*)&Bs[buf][c0][kk + 2 * t];
                bf[nt][1] = *(const uint32_t*)&Bs[buf][c0][kk + 2 * t + 8];
            }
#pragma unroll
            for (int mt = 0; mt < 2; mt++)
#pragma unroll
                for (int nt = 0; nt < 4; nt++)
                    mma16h(acc[mt][nt], af[mt], bf[nt]);
        }
        __syncthreads();
        buf ^= 1;
    }

    int cbase = blockIdx.y * GBN + wn * 32;
    const float* bp = g_bpack + l * 256;
    bool isXL = (blockIdx.y < 2);
    int coff = isXL ? cbase : cbase - DD;
#pragma unroll
    for (int mt = 0; mt < 2; mt++) {
        int r0 = bm0 + wm * 32 + mt * 16 + g;
#pragma unroll
        for (int nt = 0; nt < 4; nt++) {
            int cb = cbase + nt * 8 + 2 * t;
            int c  = coff + nt * 8 + 2 * t;
            float bx = bp[cb], by = bp[cb + 1];
            if (r0 < NN) {
                float vx = acc[mt][nt][0] + bx, vy = acc[mt][nt][1] + by;
                if (isXL) *(__half2*)(g_xlh + (size_t)r0 * DD + c) = __floats2half2_rn(vx, vy);
                else      *(float2*)(g_xr + (size_t)r0 * DD + c) = make_float2(vx, vy);
            }
            if (r0 + 8 < NN) {
                float vx = acc[mt][nt][2] + bx, vy = acc[mt][nt][3] + by;
                if (isXL) *(__half2*)(g_xlh + (size_t)(r0 + 8) * DD + c) = __floats2half2_rn(vx, vy);
                else      *(float2*)(g_xr + (size_t)(r0 + 8) * DD + c) = make_float2(vx, vy);
            }
        }
    }
}

// ---------------- GAT edge aggregation (exact R11 form: fp16 gathers, depth-1 prefetch) ----------------
__device__ __forceinline__ float lrl(float z) { return z > 0.f ? z : 0.2f * z; }

__global__ __launch_bounds__(256) void gat_kernel(const float* __restrict__ attb,
                                                  const float* __restrict__ biasb,
                                                  int outbuf) {
    int gw = (blockIdx.x * blockDim.x + threadIdx.x) >> 5;
    int lane = threadIdx.x & 31;
    if (gw >= NN) return;
    __half* hout = (outbuf == 0) ? g_bufA : g_bufB;

    int slot = lane >> 3, h = lane & 7;

    float at[16], xr[16], ac[16];
#pragma unroll
    for (int c = 0; c < 4; c++) {
        float4 a4 = ((const float4*)(attb + h * 16))[c];
        at[4 * c + 0] = a4.x; at[4 * c + 1] = a4.y; at[4 * c + 2] = a4.z; at[4 * c + 3] = a4.w;
        float4 r4 = ((const float4*)(g_xr + (size_t)gw * DD + h * 16))[c];
        xr[4 * c + 0] = r4.x; xr[4 * c + 1] = r4.y; xr[4 * c + 2] = r4.z; xr[4 * c + 3] = r4.w;
    }
#pragma unroll
    for (int c = 0; c < 16; c++) ac[c] = 0.f;

    int jb = g_rowptr[gw], je = g_rowptr[gw + 1];
    float s = 0.f;

    int jbase = jb + slot;
    int nIter = (je - jb + 3) >> 2;

    int src0 = __ldg(&g_esrc[jbase < je ? jbase : je - 1]);
    const uint4* lp0 = (const uint4*)(g_xlh + (size_t)src0 * DD + h * 16);
    uint4 u0 = __ldg(lp0), u1 = __ldg(lp0 + 1);
    int jn = jbase + 4;
    int srcn = __ldg(&g_esrc[jn < je ? jn : je - 1]);

    for (int it = 0; it < nIter; it++) {
        const uint4* lpn = (const uint4*)(g_xlh + (size_t)srcn * DD + h * 16);
        uint4 v0 = __ldg(lpn), v1 = __ldg(lpn + 1);
        jn += 4;
        srcn = __ldg(&g_esrc[jn < je ? jn : je - 1]);

        bool act = (jbase + 4 * it < je);

        float xs[16];
        {
            const __half2* hh0 = (const __half2*)&u0;
            const __half2* hh1 = (const __half2*)&u1;
#pragma unroll
            for (int k = 0; k < 4; k++) {
                float2 f = __half22float2(hh0[k]);
                xs[2 * k] = f.x; xs[2 * k + 1] = f.y;
            }
#pragma unroll
            for (int k = 0; k < 4; k++) {
                float2 f = __half22float2(hh1[k]);
                xs[8 + 2 * k] = f.x; xs[8 + 2 * k + 1] = f.y;
            }
        }

        float d = 0.f;
#pragma unroll
        for (int c = 0; c < 16; c++) d += at[c] * lrl(xs[c] + xr[c]);

        float p = act ? __expf(d) : 0.f;
        s += p;
#pragma unroll
        for (int c = 0; c < 16; c++) ac[c] += p * xs[c];

        u0 = v0; u1 = v1;
    }

    // merge 4 slots
#pragma unroll
    for (int off = 8; off <= 16; off <<= 1) {
        s += __shfl_xor_sync(0xffffffffu, s, off);
#pragma unroll
        for (int c = 0; c < 16; c++) ac[c] += __shfl_xor_sync(0xffffffffu, ac[c], off);
    }

    if (slot == 0) {
        float inv = 1.f / s;
        __half2 oh[8];
#pragma unroll
        for (int c = 0; c < 4; c++) {
            float4 b4 = ((const float4*)(biasb + h * 16))[c];
            float o0 = ac[4 * c + 0] * inv + b4.x;
            float o1 = ac[4 * c + 1] * inv + b4.y;
            float o2 = ac[4 * c + 2] * inv + b4.z;
            float o3 = ac[4 * c + 3] * inv + b4.w;
            o0 = o0 > 0.f ? o0 : (__expf(o0) - 1.f);
            o1 = o1 > 0.f ? o1 : (__expf(o1) - 1.f);
            o2 = o2 > 0.f ? o2 : (__expf(o2) - 1.f);
            o3 = o3 > 0.f ? o3 : (__expf(o3) - 1.f);
            oh[2 * c]     = __floats2half2_rn(o0, o1);
            oh[2 * c + 1] = __floats2half2_rn(o2, o3);
        }
        uint4* op = (uint4*)(hout + (size_t)gw * DD + h * 16);
        op[0] = *(uint4*)&oh[0];
        op[1] = *(uint4*)&oh[4];
    }
}

// ---------------- global mean pool (reads fp16 h) ----------------
__global__ __launch_bounds__(128) void pool_kernel(const int* __restrict__ batch) {
    int ch = threadIdx.x;
    int n0 = blockIdx.x * 128;
    int nEnd = n0 + 128; if (nEnd > NN) nEnd = NN;
    if (n0 >= NN) return;

    int cur = batch[n0];
    float acc = 0.f;
    int runlen = 0;
    for (int nd = n0; nd < nEnd; nd++) {
        int gidx = batch[nd];
        if (gidx != cur) {
            atomicAdd(&g_pool[cur * DD + ch], acc);
            if (ch == 0) atomicAdd(&g_pcnt[cur], (float)runlen);
            acc = 0.f; runlen = 0; cur = gidx;
        }
        acc += __half2float(g_bufA[(size_t)nd * DD + ch]);
        runlen++;
    }
    atomicAdd(&g_pool[cur * DD + ch], acc);
    if (ch == 0) atomicAdd(&g_pcnt[cur], (float)runlen);
}

// ---------------- classifier + log_softmax ----------------
__global__ void cls_kernel(const float* __restrict__ Wout,
                           const float* __restrict__ bout,
                           float* __restrict__ out) {
    __shared__ float slog[NG][NC];
    __shared__ float srow[NG];
    int t = threadIdx.x;
    if (t < NG * NC) {
        int g = t / NC, c = t % NC;
        float inv = 1.f / fmaxf(g_pcnt[g], 1.f);
        float acc = 0.f;
        for (int k = 0; k < DD; k++) acc += g_pool[g * DD + k] * Wout[k * NC + c];
        slog[g][c] = acc * inv + bout[c];
    }
    __syncthreads();
    if (t < NG) {
        float mx = -3.0e38f;
        for (int c = 0; c < NC; c++) mx = fmaxf(mx, slog[t][c]);
        float ssum = 0.f;
        for (int c = 0; c < NC; c++) ssum += expf(slog[t][c] - mx);
        srow[t] = mx + logf(ssum);
    }
    __syncthreads();
    if (t < NG * NC) out[t] = slog[t / NC][t % NC] - srow[t / NC];
}

// ---------------- driver ----------------
extern "C" void kernel_launch(void* const* d_in, const int* in_sizes, int n_in,
                              void* d_out, int out_size) {
    const float* x     = (const float*)d_in[0];
    const int*   ei    = (const int*)  d_in[1];
    const int*   batch = (const int*)  d_in[2];
    const float* Wl    = (const float*)d_in[3];
    const float* bl    = (const float*)d_in[4];
    const float* Wr    = (const float*)d_in[5];
    const float* br    = (const float*)d_in[6];
    const float* att   = (const float*)d_in[7];
    const float* bias  = (const float*)d_in[8];
    const float* Wout  = (const float*)d_in[9];
    const float* bout  = (const float*)d_in[10];
    float* out = (float*)d_out;

    // side stream + events for the independent CSR branch (host-side objects only)
    static cudaStream_t s2 = nullptr;
    static cudaEvent_t evFork = nullptr, evJoin = nullptr;
    if (s2 == nullptr) {
        cudaStreamCreateWithFlags(&s2, cudaStreamNonBlocking);
        cudaEventCreateWithFlags(&evFork, cudaEventDisableTiming);
        cudaEventCreateWithFlags(&evJoin, cudaEventDisableTiming);
    }

    dim3 ggrid((NN + GBM - 1) / GBM, 4);

    // fork: CSR branch on s2 runs concurrent with pack/roundx/gemm0
    cudaEventRecord(evFork, 0);
    cudaStreamWaitEvent(s2, evFork, 0);

    // submission order keeps gemm0 at kernel-launch slot #3 for ncu capture
    init_kernel<<<(NN + 255) / 256, 256, 0, s2>>>();                              // #0
    pack_kernel<<<(NL * 256 * DD + NL * 256 + 255) / 256, 256>>>(Wl, bl, Wr, br); // #1
    roundx_kernel<<<(NN * DD / 4 + 255) / 256, 256>>>(x);                         // #2
    gemm_tc_kernel<<<ggrid, 256>>>(0);                                            // #3

    count_kernel<<<(NE + 255) / 256, 256, 0, s2>>>(ei);
    scan1_kernel<<<SCAN_BLOCKS, 1024, 0, s2>>>();
    scan2_kernel<<<1, 32, 0, s2>>>();
    scan3_kernel<<<SCAN_BLOCKS, 1024, 0, s2>>>();
    scatter_kernel<<<(NE + 255) / 256, 256, 0, s2>>>(ei);
    cudaEventRecord(evJoin, s2);

    // join: everything after here needs the CSR
    cudaStreamWaitEvent(0, evJoin, 0);

    for (int l = 0; l < NL; l++) {
        if (l > 0) gemm_tc_kernel<<<ggrid, 256>>>(l);
        int outbuf = (l % 2 == 0) ? 0 : 1;
        gat_kernel<<<(NN * 32 + 255) / 256, 256>>>(att + l * DD, bias + l * DD, outbuf);
    }

    pool_kernel<<<(NN + 127) / 128, 128>>>(batch);
    cls_kernel<<<1, 640>>>(Wout, bout, out);
}